// round 17
// baseline (speedup 1.0000x reference)
#include <cuda_runtime.h>
#include <cuda_fp16.h>

// Problem constants
#define SRC_HW   64
#define CELLS    4096        // 64*64 flow cells per batch-slice
#define CH       256
#define NB       4           // output batches
#define NN       4           // accumulated slices (num)
#define HO       192         // output H = W = 3*64
#define NBB      16          // NB*NN batch-slices
#define PW       72          // padded plane width/height (4 zero border each side)
#define RW       36          // half2 words per padded row
#define REPW     (PW * RW)   // half2 words per parity replica (2592)

// Cell->position permutation per (b, z): dealt so that each aligned block of
// 32 positions has distinct n=0 SMEM banks (n=0 gather conflict-free).
__device__ unsigned short g_pos[NB * 4 * 1024];

// Per-(bb, position) metadata (stored at PERMUTED position):
//  .x = bitcast int: byte offset of patch-row base (bits 0..15)
//                    | local cell index within z-quarter (bits 16..25)
//  .y = m * (1 - ay)
//  .z = m * ay
//  .w = ax
__device__ float4 g_meta[NBB * CELLS];   // 1 MB static scratch

// Compute the n=0 bank for each cell of one (b, z) group and deal cells into
// position blocks so each 32-block covers distinct banks.
__global__ void perm_kernel(const float* __restrict__ flow) {
    int g = blockIdx.x;      // 0..15
    int b = g & 3;
    int z = g >> 2;
    int t = threadIdx.x;     // 0..255

    __shared__ int cnt[32];
    __shared__ unsigned char takenA[1024];
    __shared__ short posbuf[1024];
    __shared__ short over_l[1024];
    __shared__ short holes[1024];
    __shared__ int nover, nhole;

    if (t < 32) cnt[t] = 0;
    if (t == 0) { nover = 0; nhole = 0; }
    for (int i = t; i < 1024; i += 256) takenA[i] = 0;
    __syncthreads();

    for (int k = 0; k < 4; k++) {
        int l = t + 256 * k;
        int cell = z * 1024 + l;
        int cy = cell >> 6, cx = cell & 63;
        // n=0 slice: bb == b
        float fy = flow[((size_t)(b * 2 + 0)) * CELLS + cell];
        float fx = flow[((size_t)(b * 2 + 1)) * CELLS + cell];
        float by = (float)cy + fy;
        float bx = (float)cx + fx;
        int y0 = (int)floorf(by);
        int x0 = (int)floorf(bx);
        int yb = min(max(y0 - 1, -4), SRC_HW);
        int xb = min(max(x0 - 1, -4), SRC_HW);
        int py = yb + 4, px = xb + 4;
        int off = (px & 1) * REPW + py * RW + (px >> 1);   // word offset
        int bank = off & 31;
        int r = atomicAdd(&cnt[bank], 1);
        if (r < 32) {
            int pos = r * 32 + bank;
            posbuf[l] = (short)pos;
            takenA[pos] = 1;
        } else {
            int o = atomicAdd(&nover, 1);
            over_l[o] = (short)l;
        }
    }
    __syncthreads();
    for (int i = t; i < 1024; i += 256)
        if (!takenA[i]) { int h = atomicAdd(&nhole, 1); holes[h] = (short)i; }
    __syncthreads();
    for (int i = t; i < nover; i += 256)
        posbuf[over_l[i]] = holes[i];
    __syncthreads();
    unsigned short* gp = g_pos + (size_t)g * 1024;
    for (int i = t; i < 1024; i += 256) gp[i] = (unsigned short)posbuf[i];
}

__global__ void meta_kernel(const float* __restrict__ flow,
                            const float* __restrict__ masks) {
    int idx = blockIdx.x * blockDim.x + threadIdx.x;
    if (idx >= NBB * CELLS) return;
    int bb   = idx >> 12;
    int cell = idx & (CELLS - 1);
    int cy = cell >> 6;
    int cx = cell & 63;

    float fy = flow[((size_t)(bb * 2 + 0)) * CELLS + cell];
    float fx = flow[((size_t)(bb * 2 + 1)) * CELLS + cell];
    float m  = masks[(size_t)bb * CELLS + cell];

    float by = (float)cy + fy;
    float bx = (float)cx + fx;
    float y0f = floorf(by);
    float x0f = floorf(bx);
    float ay = by - y0f;
    float ax = bx - x0f;
    int y0 = (int)y0f;
    int x0 = (int)x0f;

    int yb = min(max(y0 - 1, -4), SRC_HW);
    int xb = min(max(x0 - 1, -4), SRC_HW);
    int py = yb + 4;                  // 0..68
    int px = xb + 4;                  // 0..68
    int mo = ((px & 1) * REPW + py * RW + (px >> 1)) * 4;  // byte offset <= 20296

    int b = bb & 3;
    int z = cell >> 10;
    int l = cell & 1023;
    int pos  = g_pos[((b * 4 + z) << 10) + l];
    int slot = (bb << 12) + (z << 10) + pos;

    g_meta[slot] = make_float4(__int_as_float(mo | (l << 16)),
                               m * (1.0f - ay), m * ay, ax);
}

static __device__ __forceinline__ unsigned pack_h2(float a, float b) {
    __half2 h = __floats2half2_rn(a, b);
    return *reinterpret_cast<unsigned*>(&h);
}

// One block per (channel, batch, cell-quarter). Source plane prefetched into
// registers, converted to fp16 and written to BOTH x-parity replicas from
// registers. Patch rows are 2 LDS.32 from the parity-matched replica.
// Cells are permuted per (b,z) so n=0 gathers are bank-conflict-free.
__global__ __launch_bounds__(256, 3)
void extract_kernel(const float* __restrict__ src, float* __restrict__ out) {
    const int c = blockIdx.x;   // 0..255
    const int b = blockIdx.y;   // 0..3
    const int z = blockIdx.z;   // 0..3  (cell quarter)
    const int t = threadIdx.x;  // 0..255

    __shared__ __align__(16) unsigned rep[2 * REPW];   // 20736 B

    // Zero everything once (borders stay zero; interiors overwritten per n).
    {
        uint4 z4 = make_uint4(0u, 0u, 0u, 0u);
        uint4* rz = (uint4*)rep;
        for (int i = t; i < (2 * REPW) / 4; i += 256) rz[i] = z4;
    }

    float acc[4][9];
#pragma unroll
    for (int j = 0; j < 4; j++)
#pragma unroll
        for (int q = 0; q < 9; q++) acc[j][q] = 0.0f;

    const int cell0 = z * 1024;

    // Prefetch plane n=0, converting to packed fp16 immediately (8 regs).
    unsigned u[8];
    {
        const float4* sp = (const float4*)(src + ((size_t)(b * CH + c)) * CELLS);
#pragma unroll
        for (int k = 0; k < 4; k++) {
            float4 v = sp[t + 256 * k];
            u[2 * k]     = pack_h2(v.x, v.y);
            u[2 * k + 1] = pack_h2(v.z, v.w);
        }
    }

    for (int n = 0; n < NN; n++) {
        __syncthreads();   // previous gather (or zeroing) done before overwrite
        const int bb = n * NB + b;

        // Fill both replicas from registers. Warp lanes cover consecutive
        // float4s; each warp spans exactly 2 source rows, so the row-end lane
        // (col4==15) substitutes the zero border.
#pragma unroll
        for (int k = 0; k < 4; k++) {
            int i    = t + 256 * k;
            int row  = i >> 4;
            int col4 = i & 15;
            unsigned u0 = u[2 * k];
            unsigned u1 = u[2 * k + 1];
            unsigned nb = __shfl_down_sync(0xffffffffu, u0, 1);
            if (col4 == 15) nb = 0u;

            int base = (row + 4) * RW + 2 + 2 * col4;   // even -> 8B aligned
            *(uint2*)&rep[base] = make_uint2(u0, u1);
            *(uint2*)&rep[REPW + base] =
                make_uint2((u0 >> 16) | (u1 << 16), (u1 >> 16) | (nb << 16));
            if (col4 == 0)   // boundary word (border0, h0) at word index 1
                rep[REPW + (row + 4) * RW + 1] = (u0 & 0xFFFFu) << 16;
        }

        // Prefetch+convert next plane while this one is gathered.
        if (n < NN - 1) {
            const float4* sp = (const float4*)(src +
                ((size_t)(((n + 1) * NB + b) * CH + c)) * CELLS);
#pragma unroll
            for (int k = 0; k < 4; k++) {
                float4 v = sp[t + 256 * k];
                u[2 * k]     = pack_h2(v.x, v.y);
                u[2 * k + 1] = pack_h2(v.z, v.w);
            }
        }
        __syncthreads();

        const float4* __restrict__ metaB = g_meta + (size_t)bb * CELLS + cell0;

#pragma unroll
        for (int j = 0; j < 4; j++) {
            float4 mt = metaB[t + 256 * j];
            unsigned off = (unsigned)__float_as_int(mt.x) & 0xFFFFu;
            const __half2* __restrict__ p =
                (const __half2*)((const char*)rep + off);
            float wv0 = mt.y, wv1 = mt.z, ax = mt.w;

            // 4x4 patch: 2 LDS.32 per row
            float2 r0a = __half22float2(p[0]);
            float2 r0b = __half22float2(p[1]);
            float2 r1a = __half22float2(p[RW]);
            float2 r1b = __half22float2(p[RW + 1]);
            float2 r2a = __half22float2(p[2 * RW]);
            float2 r2b = __half22float2(p[2 * RW + 1]);
            float2 r3a = __half22float2(p[3 * RW]);
            float2 r3b = __half22float2(p[3 * RW + 1]);

            // Horizontal lerps (v0..v3 = a.x, a.y, b.x, b.y)
            float h0[3], h1[3], h2[3], h3[3];
            h0[0] = fmaf(ax, r0a.y - r0a.x, r0a.x);
            h0[1] = fmaf(ax, r0b.x - r0a.y, r0a.y);
            h0[2] = fmaf(ax, r0b.y - r0b.x, r0b.x);
            h1[0] = fmaf(ax, r1a.y - r1a.x, r1a.x);
            h1[1] = fmaf(ax, r1b.x - r1a.y, r1a.y);
            h1[2] = fmaf(ax, r1b.y - r1b.x, r1b.x);
            h2[0] = fmaf(ax, r2a.y - r2a.x, r2a.x);
            h2[1] = fmaf(ax, r2b.x - r2a.y, r2a.y);
            h2[2] = fmaf(ax, r2b.y - r2b.x, r2b.x);
            h3[0] = fmaf(ax, r3a.y - r3a.x, r3a.x);
            h3[1] = fmaf(ax, r3b.x - r3a.y, r3a.y);
            h3[2] = fmaf(ax, r3b.y - r3b.x, r3b.x);

            // Masked vertical FMAs
#pragma unroll
            for (int q = 0; q < 3; q++) {
                acc[j][0 + q] = fmaf(wv1, h1[q], fmaf(wv0, h0[q], acc[j][0 + q]));
                acc[j][3 + q] = fmaf(wv1, h2[q], fmaf(wv0, h1[q], acc[j][3 + q]));
                acc[j][6 + q] = fmaf(wv1, h3[q], fmaf(wv0, h2[q], acc[j][6 + q]));
            }
        }
    }

    // Write 4 cells x 3x3 outputs. Cell index comes from the permuted meta
    // (high bits of .x, same for all n — reload from the n=0 slice).
    float* ob = out + ((size_t)(b * CH + c)) * (HO * HO);
    const float4* __restrict__ metaB0 = g_meta + (size_t)b * CELLS + cell0;
#pragma unroll
    for (int j = 0; j < 4; j++) {
        int mx = __float_as_int(metaB0[t + 256 * j].x);
        int cell = cell0 + ((mx >> 16) & 1023);
        int cy = cell >> 6;
        int cx = cell & 63;
#pragma unroll
        for (int i = 0; i < 3; i++) {
            float* row = ob + (size_t)(cy * 3 + i) * HO + cx * 3;
            row[0] = acc[j][i * 3 + 0];
            row[1] = acc[j][i * 3 + 1];
            row[2] = acc[j][i * 3 + 2];
        }
    }
}

extern "C" void kernel_launch(void* const* d_in, const int* in_sizes, int n_in,
                              void* d_out, int out_size) {
    const float* src   = (const float*)d_in[0];  // (16, 256, 64, 64)
    const float* flow  = (const float*)d_in[1];  // (16, 2, 64, 64)
    const float* masks = (const float*)d_in[2];  // (16, 1, 64, 64)
    float* out = (float*)d_out;                  // (4, 256, 192, 192)

    perm_kernel<<<16, 256>>>(flow);
    meta_kernel<<<(NBB * CELLS + 255) / 256, 256>>>(flow, masks);

    dim3 grid(CH, NB, 4);
    extract_kernel<<<grid, 256>>>(src, out);
}